// round 17
// baseline (speedup 1.0000x reference)
#include <cuda_runtime.h>

#define FULLMASK 0xFFFFFFFFu
typedef unsigned long long u64;

__device__ float g_partial[4096];
__device__ int g_count = 0;

// ---- f32x2 packed helpers (sm_100+) ----
static __device__ __forceinline__ u64 pk(float lo, float hi) {
    u64 r; asm("mov.b64 %0, {%1, %2};" : "=l"(r) : "f"(lo), "f"(hi)); return r;
}
static __device__ __forceinline__ float f2lo(u64 v) {
    float a, b; asm("mov.b64 {%0, %1}, %2;" : "=f"(a), "=f"(b) : "l"(v)); return a;
}
static __device__ __forceinline__ float f2hi(u64 v) {
    float a, b; asm("mov.b64 {%0, %1}, %2;" : "=f"(a), "=f"(b) : "l"(v)); return b;
}
static __device__ __forceinline__ u64 fma2(u64 a, u64 b, u64 c) {
    u64 d; asm("fma.rn.f32x2 %0, %1, %2, %3;" : "=l"(d) : "l"(a), "l"(b), "l"(c)); return d;
}
static __device__ __forceinline__ u64 mul2(u64 a, u64 b) {
    u64 d; asm("mul.rn.f32x2 %0, %1, %2;" : "=l"(d) : "l"(a), "l"(b)); return d;
}

// 8 lanes per element, 8 states per lane (states 8s+1..8s+8).
// D-chain segment for lane s maps fD[8s+1] -> fD[8s+9] using only OWN fMn.
// 5 shuffles/step (width 8), fully branchless.
#define PHMM_STEP(XL) do {                                                       \
    const int xl = (XL);                                                         \
    const float4 ev0 = *(const float4*)(myt + ((xl) << 6) + R0);                 \
    const float4 ev1 = *(const float4*)(myt + ((xl) << 6) + R0 + 4);             \
    u64 prevA = fma2(tM2M0, fMa, fma2(tI2M0, fIa, mul2(tD2M0, fDa)));            \
    u64 prevB = fma2(tM2M1, fMb, fma2(tI2M1, fIb, mul2(tD2M1, fDb)));            \
    u64 prevC = fma2(tM2M2, fMc, fma2(tI2M2, fIc, mul2(tD2M2, fDc)));            \
    u64 prevD = fma2(tM2M3, fMd, fma2(tI2M3, fId, mul2(tD2M3, fDd)));            \
    float prevUp = __shfl_up_sync(FULLMASK, f2hi(prevD), 1, 8);                  \
    float base0 = fmaf(sM2M0, fM0v, sI2M0 * fI0v);                               \
    prevUp = isSub0 ? base0 : prevUp;                                            \
    u64 Fa = mul2(pk(ev0.x, ev0.y), pk(prevUp,     f2lo(prevA)));                \
    u64 Fb = mul2(pk(ev0.z, ev0.w), pk(f2hi(prevA), f2lo(prevB)));               \
    u64 Fc = mul2(pk(ev1.x, ev1.y), pk(f2hi(prevB), f2lo(prevC)));               \
    u64 Fd = mul2(pk(ev1.z, ev1.w), pk(f2hi(prevC), f2lo(prevD)));               \
    float f0 = f2lo(Fa), f1 = f2hi(Fa), f2v = f2lo(Fb), f3 = f2hi(Fb);           \
    float f4 = f2lo(Fc), f5 = f2hi(Fc), f6 = f2lo(Fd), f7 = f2hi(Fd);            \
    /* r-chain over f1..f7: independent of the shuffled f0 */                    \
    float r1 = mm1 * f1;                                                         \
    float r2 = fmaf(dd2, r1, mm2 * f2v);                                         \
    float r3 = fmaf(dd3, r2, mm3 * f3);                                          \
    float r4 = fmaf(dd4, r3, mm4 * f4);                                          \
    float r5 = fmaf(dd5, r4, mm5 * f5);                                          \
    float r6 = fmaf(dd6, r5, mm6 * f6);                                          \
    float r7 = fmaf(dd7, r6, mm7 * f7);                                          \
    float t0 = mm0 * f0;                                                         \
    float t1 = fmaf(c01, f0, r1);                                                \
    float t2 = fmaf(c02, f0, r2);                                                \
    float t3 = fmaf(c03, f0, r3);                                                \
    float t4 = fmaf(c04, f0, r4);                                                \
    float t5 = fmaf(c05, f0, r5);                                                \
    float t6 = fmaf(c06, f0, r6);                                                \
    float Bc = fmaf(c07, f0, r7);                                                \
    float Bu;                                                                    \
    Bu = __shfl_up_sync(FULLMASK, Bc, 1, 8); Bc = fmaf(Ak0, Bu, Bc);             \
    Bu = __shfl_up_sync(FULLMASK, Bc, 2, 8); Bc = fmaf(Ak1, Bu, Bc);             \
    Bu = __shfl_up_sync(FULLMASK, Bc, 4, 8); Bc = fmaf(Ak2, Bu, Bc);             \
    float fDp = __shfl_up_sync(FULLMASK, Bc, 1, 8) * edge;  /* 0 at sub==0 */    \
    u64 fIna = fma2(tM2I0, fMa, mul2(tI2I0, fIa));                               \
    u64 fInb = fma2(tM2I1, fMb, mul2(tI2I1, fIb));                               \
    u64 fInc = fma2(tM2I2, fMc, mul2(tI2I2, fIc));                               \
    u64 fInd = fma2(tM2I3, fMd, mul2(tI2I3, fId));                               \
    float fI0n = fmaf(sM2I0, fM0v, sI2I0 * fI0v);                                \
    fMa = Fa; fMb = Fb; fMc = Fc; fMd = Fd;                                      \
    fIa = fIna; fIb = fInb; fIc = fInc; fId = fInd;                              \
    fI0v = fI0n; fM0v = 0.f;                                                     \
    fDa = pk(fDp, fmaf(AA0, fDp, t0));                                           \
    fDb = pk(fmaf(AA1, fDp, t1), fmaf(AA2, fDp, t2));                            \
    fDc = pk(fmaf(AA3, fDp, t3), fmaf(AA4, fDp, t4));                            \
    fDd = pk(fmaf(AA5, fDp, t5), fmaf(AA6, fDp, t6));                            \
} while (0)

#define PHMM_RESCALE do {                                                        \
    float m = fmaxf(fmaxf(f2lo(fMa), f2hi(fMa)), fmaxf(f2lo(fMb), f2hi(fMb)));   \
    m = fmaxf(m, fmaxf(fmaxf(f2lo(fMc), f2hi(fMc)), fmaxf(f2lo(fMd), f2hi(fMd)))); \
    m = fmaxf(m, fmaxf(fmaxf(f2lo(fIa), f2hi(fIa)), fmaxf(f2lo(fIb), f2hi(fIb)))); \
    m = fmaxf(m, fmaxf(fmaxf(f2lo(fIc), f2hi(fIc)), fmaxf(f2lo(fId), f2hi(fId)))); \
    m = fmaxf(m, fmaxf(fmaxf(f2lo(fDa), f2hi(fDa)), fmaxf(f2lo(fDb), f2hi(fDb)))); \
    m = fmaxf(m, fmaxf(fmaxf(f2lo(fDc), f2hi(fDc)), fmaxf(f2lo(fDd), f2hi(fDd)))); \
    m = fmaxf(m, fI0v);                                                          \
    m = fmaxf(m, __shfl_xor_sync(FULLMASK, m, 4, 8));                            \
    m = fmaxf(m, __shfl_xor_sync(FULLMASK, m, 2, 8));                            \
    m = fmaxf(m, __shfl_xor_sync(FULLMASK, m, 1, 8));                            \
    int be = __float_as_int(m) >> 23;                                            \
    Ci += be - 127;                                                              \
    float r = __int_as_float((254 - be) << 23);                                  \
    u64 r2 = pk(r, r);                                                           \
    fMa = mul2(fMa, r2); fMb = mul2(fMb, r2); fMc = mul2(fMc, r2); fMd = mul2(fMd, r2); \
    fIa = mul2(fIa, r2); fIb = mul2(fIb, r2); fIc = mul2(fIc, r2); fId = mul2(fId, r2); \
    fDa = mul2(fDa, r2); fDb = mul2(fDb, r2); fDc = mul2(fDc, r2); fDd = mul2(fDd, r2); \
    fI0v *= r;                                                                   \
} while (0)

__global__ void __launch_bounds__(128, 4) phmm_fused_kernel(
    const int* __restrict__ xg, const float* __restrict__ ag,
    const float* __restrict__ eg, const float* __restrict__ mug,
    const float* __restrict__ lvg, float* __restrict__ outp)
{
    const int lane = threadIdx.x & 31;
    const int warp = threadIdx.x >> 5;
    const int sub  = lane & 7;                 // lane within 8-lane group
    const int eidx = threadIdx.x >> 3;         // element within block: 0..15
    const int b = (blockIdx.x << 4) + eidx;
    const bool isSub0 = (sub == 0);
    const float edge = isSub0 ? 0.f : 1.f;

    // per-element emission table: [4 syms][64 states] floats = 1KB; 16 KB/block
    __shared__ float etab[16 * 256];
    float* myt = etab + (eidx << 8);

    const float* ab  = ag + b * 455;     // (65,7)
    const float* ebp = eg + (b << 8);    // (64,4)

    const int R0 = sub << 3;             // first owned e-row / state base 8s

    // transition rows 8s+1..8s+8
    float aM2M[8], aM2I[8], aI2M[8], aI2I[8], aD2M[8], mmv[8], ddv[8];
    #pragma unroll
    for (int j = 0; j < 8; ++j) {
        const float* pr = ab + (R0 + 1 + j) * 7;
        aM2M[j] = __expf(pr[0]);
        aM2I[j] = 0.25f * __expf(pr[1]);
        mmv[j]  = __expf(pr[2]);
        aI2M[j] = __expf(pr[3]);
        aI2I[j] = 0.25f * __expf(pr[4]);
        aD2M[j] = __expf(pr[5]);
        ddv[j]  = __expf(pr[6]);
    }
    const u64 tM2M0 = pk(aM2M[0], aM2M[1]), tM2M1 = pk(aM2M[2], aM2M[3]);
    const u64 tM2M2 = pk(aM2M[4], aM2M[5]), tM2M3 = pk(aM2M[6], aM2M[7]);
    const u64 tM2I0 = pk(aM2I[0], aM2I[1]), tM2I1 = pk(aM2I[2], aM2I[3]);
    const u64 tM2I2 = pk(aM2I[4], aM2I[5]), tM2I3 = pk(aM2I[6], aM2I[7]);
    const u64 tI2M0 = pk(aI2M[0], aI2M[1]), tI2M1 = pk(aI2M[2], aI2M[3]);
    const u64 tI2M2 = pk(aI2M[4], aI2M[5]), tI2M3 = pk(aI2M[6], aI2M[7]);
    const u64 tI2I0 = pk(aI2I[0], aI2I[1]), tI2I1 = pk(aI2I[2], aI2I[3]);
    const u64 tI2I2 = pk(aI2I[4], aI2I[5]), tI2I3 = pk(aI2I[6], aI2I[7]);
    const u64 tD2M0 = pk(aD2M[0], aD2M[1]), tD2M1 = pk(aD2M[2], aD2M[3]);
    const u64 tD2M2 = pk(aD2M[4], aD2M[5]), tD2M3 = pk(aD2M[6], aD2M[7]);

    const float mm0 = mmv[0], mm1 = mmv[1], mm2 = mmv[2], mm3 = mmv[3];
    const float mm4 = mmv[4], mm5 = mmv[5], mm6 = mmv[6], mm7 = mmv[7];
    const float dd2 = ddv[2], dd3 = ddv[3], dd4 = ddv[4];
    const float dd5 = ddv[5], dd6 = ddv[6], dd7 = ddv[7];

    // qp_j = dd1..ddj ; c0_j = mm0*qp_j ; AA_j = dd0*qp_j ; Alane = AA7
    float qp1 = ddv[1];
    float qp2 = qp1 * dd2, qp3 = qp2 * dd3, qp4 = qp3 * dd4;
    float qp5 = qp4 * dd5, qp6 = qp5 * dd6, qp7 = qp6 * dd7;
    const float c01 = mm0 * qp1, c02 = mm0 * qp2, c03 = mm0 * qp3;
    const float c04 = mm0 * qp4, c05 = mm0 * qp5, c06 = mm0 * qp6, c07 = mm0 * qp7;
    const float AA0 = ddv[0];
    const float AA1 = AA0 * qp1, AA2 = AA0 * qp2, AA3 = AA0 * qp3;
    const float AA4 = AA0 * qp4, AA5 = AA0 * qp5, AA6 = AA0 * qp6;
    const float Alane = AA0 * qp7;

    // state-0 scalars + m00 for initial D chain
    const float sM2M0 = __expf(ab[0]);
    const float sM2I0 = 0.25f * __expf(ab[1]);
    const float m00   = __expf(ab[2]);
    const float sI2M0 = __expf(ab[3]);
    const float sI2I0 = 0.25f * __expf(ab[4]);

    // emissions rows 8s..8s+7 -> smem table [sym][state]
    #pragma unroll
    for (int j = 0; j < 8; ++j) {
        float4 er = __ldg((const float4*)(ebp + ((R0 + j) << 2)));
        myt[      R0 + j] = __expf(er.x);
        myt[ 64 + R0 + j] = __expf(er.y);
        myt[128 + R0 + j] = __expf(er.z);
        myt[192 + R0 + j] = __expf(er.w);
    }
    __syncwarp();   // table written/read within the same warp

    // pack symbols: lane sub holds word = symbols [16*sub .. 16*sub+15], 2b each
    int word;
    {
        const int* xb = xg + (b << 7) + (sub << 4);
        const int4 xa = *(const int4*)(xb);
        const int4 xb2 = *(const int4*)(xb + 4);
        const int4 xc = *(const int4*)(xb + 8);
        const int4 xd = *(const int4*)(xb + 12);
        word = xa.x | (xa.y << 2) | (xa.z << 4) | (xa.w << 6)
             | (xb2.x << 8) | (xb2.y << 10) | (xb2.z << 12) | (xb2.w << 14)
             | (xc.x << 16) | (xc.y << 18) | (xc.z << 20) | (xc.w << 22)
             | (xd.x << 24) | (xd.y << 26) | (xd.z << 28) | (xd.w << 30);
    }

    // Kogge-Stone A-side over 8 lanes; zeroed below each level's horizon
    float Ak0, Ak1, Ak2;
    {
        float Ac = Alane;
        Ak0 = (sub >= 1) ? Ac : 0.f;
        float Au = __shfl_up_sync(FULLMASK, Ac, 1, 8);
        Ac *= (sub >= 1) ? Au : 1.f;
        Ak1 = (sub >= 2) ? Ac : 0.f;
        Au = __shfl_up_sync(FULLMASK, Ac, 2, 8);
        Ac *= (sub >= 2) ? Au : 1.f;
        Ak2 = (sub >= 4) ? Ac : 0.f;
    }

    // state (scaled linear space)
    u64 fMa = pk(0.f, 0.f), fMb = fMa, fMc = fMa, fMd = fMa;
    u64 fIa = fMa, fIb = fMa, fIc = fMa, fId = fMa;
    u64 fDa, fDb, fDc, fDd;
    float fM0v = 1.f, fI0v = 0.f;
    int Ci = 0;

    // initial D chain: fD[1] = m00, propagate via A-products only
    {
        float Bc = isSub0 ? (Alane * m00) : 0.f;
        float Bu;
        Bu = __shfl_up_sync(FULLMASK, Bc, 1, 8); Bc = fmaf(Ak0, Bu, Bc);
        Bu = __shfl_up_sync(FULLMASK, Bc, 2, 8); Bc = fmaf(Ak1, Bu, Bc);
        Bu = __shfl_up_sync(FULLMASK, Bc, 4, 8); Bc = fmaf(Ak2, Bu, Bc);
        float fDp = __shfl_up_sync(FULLMASK, Bc, 1, 8);
        float fDs = isSub0 ? m00 : fDp;
        fDa = pk(fDs, AA0 * fDs);
        fDb = pk(AA1 * fDs, AA2 * fDs);
        fDc = pk(AA3 * fDs, AA4 * fDs);
        fDd = pk(AA5 * fDs, AA6 * fDs);
    }

    // ---- main loop: 8 words x 16 symbols; rescale every 8 steps ----
    #pragma unroll 1
    for (int wi = 0; wi < 8; ++wi) {
        int w = __shfl_sync(FULLMASK, word, wi, 8);
        #pragma unroll
        for (int i = 0; i < 8; ++i) { PHMM_STEP(w & 3); w >>= 2; }
        PHMM_RESCALE;
        #pragma unroll
        for (int i = 0; i < 8; ++i) { PHMM_STEP(w & 3); w >>= 2; }
        PHMM_RESCALE;
    }

    // final = fM[64]*M2M[64] + fI[64]*I2M[64] + fD[64]*D2M[64] : sub=7, hi slot
    u64 fin2 = fma2(tM2M3, fMd, fma2(tI2M3, fId, mul2(tD2M3, fDd)));
    float loss = -(__logf(f2hi(fin2)) + (float)Ci * 0.6931471805599453f);
    loss = __shfl_sync(FULLMASK, loss, 7, 8);   // broadcast within group

    // KLD: 16 values per element, 2 per lane
    float2 mv = ((const float2*)mug)[(b << 3) + sub];
    float2 lv = ((const float2*)lvg)[(b << 3) + sub];
    float kt = (1.f + lv.x - mv.x * mv.x - __expf(lv.x))
             + (1.f + lv.y - mv.y * mv.y - __expf(lv.y));
    kt += __shfl_xor_sync(FULLMASK, kt, 4, 8);
    kt += __shfl_xor_sync(FULLMASK, kt, 2, 8);
    kt += __shfl_xor_sync(FULLMASK, kt, 1, 8);

    if (isSub0) g_partial[b] = loss - 0.5f * kt;

    // ---- fused deterministic final reduction (last-block pattern) ----
    __shared__ float ws[4];
    __shared__ int isLast;
    __syncthreads();
    if (threadIdx.x == 0) {
        __threadfence();
        isLast = (atomicAdd(&g_count, 1) == (int)gridDim.x - 1);
    }
    __syncthreads();
    if (isLast) {
        const float4* gp = (const float4*)g_partial;
        float s = 0.f;
        #pragma unroll
        for (int i = 0; i < 8; ++i) {
            float4 v = gp[threadIdx.x + (i << 7)];
            s += (v.x + v.y) + (v.z + v.w);
        }
        s += __shfl_xor_sync(FULLMASK, s, 16);
        s += __shfl_xor_sync(FULLMASK, s, 8);
        s += __shfl_xor_sync(FULLMASK, s, 4);
        s += __shfl_xor_sync(FULLMASK, s, 2);
        s += __shfl_xor_sync(FULLMASK, s, 1);
        if (lane == 0) ws[warp] = s;
        __syncthreads();
        if (threadIdx.x == 0) {
            float t = ws[0] + ws[1] + ws[2] + ws[3];
            *outp = t * (1.0f / 4096.0f);
            g_count = 0;   // reset for next graph replay
        }
    }
}

extern "C" void kernel_launch(void* const* d_in, const int* in_sizes, int n_in,
                              void* d_out, int out_size)
{
    const int*   x   = (const int*)d_in[0];
    const float* a   = (const float*)d_in[1];
    const float* e   = (const float*)d_in[2];
    const float* mus = (const float*)d_in[3];
    const float* lvs = (const float*)d_in[4];

    phmm_fused_kernel<<<256, 128>>>(x, a, e, mus, lvs, (float*)d_out);
}